// round 2
// baseline (speedup 1.0000x reference)
#include <cuda_runtime.h>
#include <cstddef>

#define W_    256
#define HW_   65536
#define C_    64
#define B_    16
#define NTOT_ (B_ * C_ * HW_)   // 67108864

// Scratch (allocation-free contract: __device__ globals)
__device__ float g_bufA[NTOT_];
__device__ float g_bufB[NTOT_];
__device__ int   g_maxbits[4];        // max|x|, max|y1|, max|y2|, max|y3| as float bits
__device__ float g_wq_p1[C_ * C_];
__device__ float g_wq_f1[C_ * 9];
__device__ float g_wq_p2[C_ * C_];
__device__ float g_wq_f2[C_ * 9];

// ---------------------------------------------------------------------------
// Prep: zero activation-max slots, fake-quantize the 4 weight tensors (4-bit)
// ---------------------------------------------------------------------------
__device__ void quant_weight(const float* __restrict__ src, float* __restrict__ dst,
                             int n, float* red, int t) {
    float m = 0.f;
    for (int i = t; i < n; i += 256) m = fmaxf(m, fabsf(src[i]));
    red[t] = m;
    __syncthreads();
    for (int s = 128; s > 0; s >>= 1) {
        if (t < s) red[t] = fmaxf(red[t], red[t + s]);
        __syncthreads();
    }
    float scale = red[0] / 7.0f + 1e-12f;
    __syncthreads();   // everyone read red[0] before it is reused
    for (int i = t; i < n; i += 256) {
        float q = rintf(src[i] / scale);
        q = fminf(fmaxf(q, -7.f), 7.f);
        dst[i] = q * scale;
    }
}

__global__ void prep_kernel(const float* __restrict__ wp1, const float* __restrict__ wf1,
                            const float* __restrict__ wp2, const float* __restrict__ wf2) {
    __shared__ float red[256];
    int t = threadIdx.x;
    if (t < 4) g_maxbits[t] = 0;
    quant_weight(wp1, g_wq_p1, C_ * C_, red, t);
    quant_weight(wf1, g_wq_f1, C_ * 9,  red, t);
    quant_weight(wp2, g_wq_p2, C_ * C_, red, t);
    quant_weight(wf2, g_wq_f2, C_ * 9,  red, t);
}

// ---------------------------------------------------------------------------
// Global max|x| reduction (slot 0)
// ---------------------------------------------------------------------------
__global__ void __launch_bounds__(256) kmax_x(const float* __restrict__ x) {
    float m = 0.f;
    const float4* x4 = (const float4*)x;
    size_t stride = (size_t)gridDim.x * blockDim.x;
    for (size_t i = (size_t)blockIdx.x * blockDim.x + threadIdx.x; i < NTOT_ / 4; i += stride) {
        float4 v = x4[i];
        m = fmaxf(m, fmaxf(fmaxf(fabsf(v.x), fabsf(v.y)), fmaxf(fabsf(v.z), fabsf(v.w))));
    }
    for (int o = 16; o; o >>= 1) m = fmaxf(m, __shfl_xor_sync(0xffffffffu, m, o));
    __shared__ float red[8];
    if ((threadIdx.x & 31) == 0) red[threadIdx.x >> 5] = m;
    __syncthreads();
    if (threadIdx.x < 8) {
        m = red[threadIdx.x];
        for (int o = 4; o; o >>= 1) m = fmaxf(m, __shfl_xor_sync(0xffu, m, o));
        if (threadIdx.x == 0) atomicMax(&g_maxbits[0], __float_as_int(m));
    }
}

// ---------------------------------------------------------------------------
// 1x1 conv = GEMM: out[b,co,p] = sum_ci wq[co,ci] * fq(in[b,ci,p])
// Block: one batch image, 128-pixel tile, all 64 cout. 256 threads (16x16).
// Fused: per-tensor activation quant on load + output |max| into slot_out.
// ---------------------------------------------------------------------------
__global__ void __launch_bounds__(256)
conv1x1_kernel(const float* __restrict__ in, float* __restrict__ out,
               const float* __restrict__ wq, int slot_in, int slot_out) {
    __shared__ float xs[64 * 128];   // [cin][pix]
    __shared__ float ws[64 * 64];    // [cin][cout]
    __shared__ float redm[8];

    int t    = threadIdx.x;
    int tile = blockIdx.x;           // 0..511
    int b    = blockIdx.y;           // 0..15

    float s = __int_as_float(g_maxbits[slot_in]) / 127.0f + 1e-12f;

    // Load W transposed: ws[ci][co] = wq[co*64+ci] (L2-resident)
    for (int i = t; i < C_ * C_; i += 256) {
        int co = i & 63, ci = i >> 6;
        ws[ci * 64 + co] = wq[co * 64 + ci];
    }

    // Load + quantize X tile: 64 rows x 128 pixels
    const float* src = in + (size_t)b * C_ * HW_ + tile * 128;
    #pragma unroll
    for (int i = 0; i < 8; i++) {
        int e4  = t + i * 256;         // float4 index, 0..2047
        int row = e4 >> 5;             // 32 float4 per row
        int c4  = e4 & 31;
        float4 v = *(const float4*)(src + (size_t)row * HW_ + c4 * 4);
        float qx = fminf(fmaxf(rintf(v.x / s), -127.f), 127.f) * s;
        float qy = fminf(fmaxf(rintf(v.y / s), -127.f), 127.f) * s;
        float qz = fminf(fmaxf(rintf(v.z / s), -127.f), 127.f) * s;
        float qw = fminf(fmaxf(rintf(v.w / s), -127.f), 127.f) * s;
        *(float4*)&xs[row * 128 + c4 * 4] = make_float4(qx, qy, qz, qw);
    }
    __syncthreads();

    int tx = t & 15;    // pixel group: pixels tx*8 .. tx*8+7
    int ty = t >> 4;    // cout group:  couts ty*4 .. ty*4+3
    float acc[4][8];
    #pragma unroll
    for (int i = 0; i < 4; i++)
        #pragma unroll
        for (int j = 0; j < 8; j++) acc[i][j] = 0.f;

    #pragma unroll 4
    for (int k = 0; k < 64; k++) {
        float4 w4 = *(const float4*)&ws[k * 64 + ty * 4];
        float4 x0 = *(const float4*)&xs[k * 128 + tx * 8];
        float4 x1 = *(const float4*)&xs[k * 128 + tx * 8 + 4];
        float wv[4] = {w4.x, w4.y, w4.z, w4.w};
        float xv[8] = {x0.x, x0.y, x0.z, x0.w, x1.x, x1.y, x1.z, x1.w};
        #pragma unroll
        for (int i = 0; i < 4; i++)
            #pragma unroll
            for (int j = 0; j < 8; j++) acc[i][j] += wv[i] * xv[j];
    }

    float lmax = 0.f;
    size_t obase = (size_t)b * C_ * HW_ + tile * 128 + tx * 8;
    #pragma unroll
    for (int i = 0; i < 4; i++) {
        int co = ty * 4 + i;
        #pragma unroll
        for (int j = 0; j < 8; j++) lmax = fmaxf(lmax, fabsf(acc[i][j]));
        *(float4*)(out + obase + (size_t)co * HW_)     = make_float4(acc[i][0], acc[i][1], acc[i][2], acc[i][3]);
        *(float4*)(out + obase + (size_t)co * HW_ + 4) = make_float4(acc[i][4], acc[i][5], acc[i][6], acc[i][7]);
    }

    // block max -> atomic
    for (int o = 16; o; o >>= 1) lmax = fmaxf(lmax, __shfl_xor_sync(0xffffffffu, lmax, o));
    if ((t & 31) == 0) redm[t >> 5] = lmax;
    __syncthreads();
    if (t < 8) {
        lmax = redm[t];
        for (int o = 4; o; o >>= 1) lmax = fmaxf(lmax, __shfl_xor_sync(0xffu, lmax, o));
        if (t == 0) atomicMax(&g_maxbits[slot_out], __float_as_int(lmax));
    }
}

// ---------------------------------------------------------------------------
// Depthwise 3x3 (pad 1) + PReLU (+ optional residual) + optional out-max.
// Block: 32x32 output tile of one (b,c) plane; 256 threads.
// ---------------------------------------------------------------------------
__global__ void __launch_bounds__(256)
dwconv_kernel(const float* __restrict__ in, float* __restrict__ out,
              const float* __restrict__ wq, const float* __restrict__ alpha,
              const float* __restrict__ residual,
              int slot_in, int slot_out) {
    __shared__ float tile[34 * 36];
    __shared__ float redm[8];

    int t  = threadIdx.x;
    int bx = blockIdx.x;          // 0..63 : 8x8 tiles per plane
    int c  = blockIdx.y;
    int b  = blockIdx.z;
    int tx0 = (bx & 7) << 5;
    int ty0 = (bx >> 3) << 5;

    float s = __int_as_float(g_maxbits[slot_in]) / 127.0f + 1e-12f;
    const float* base = in + ((size_t)(b * C_ + c)) * HW_;

    for (int i = t; i < 34 * 34; i += 256) {
        int r  = i / 34;
        int cc = i - r * 34;
        int gy = ty0 + r - 1;
        int gx = tx0 + cc - 1;
        float v = 0.f;
        if (gy >= 0 && gy < W_ && gx >= 0 && gx < W_) v = base[gy * W_ + gx];
        float q = fminf(fmaxf(rintf(v / s), -127.f), 127.f);
        tile[r * 36 + cc] = q * s;
    }
    __syncthreads();

    float w[9];
    #pragma unroll
    for (int k = 0; k < 9; k++) w[k] = wq[c * 9 + k];
    float a = alpha[c];

    float lmax = 0.f;
    size_t obase = ((size_t)(b * C_ + c)) * HW_;
    #pragma unroll
    for (int it = 0; it < 4; it++) {
        int i  = t + it * 256;
        int r  = i >> 5;
        int cc = i & 31;
        float acc = 0.f;
        #pragma unroll
        for (int kh = 0; kh < 3; kh++)
            #pragma unroll
            for (int kw = 0; kw < 3; kw++)
                acc += w[kh * 3 + kw] * tile[(r + kh) * 36 + cc + kw];
        float v = acc > 0.f ? acc : a * acc;
        if (residual) v += residual[obase + (size_t)(ty0 + r) * W_ + tx0 + cc];
        out[obase + (size_t)(ty0 + r) * W_ + tx0 + cc] = v;
        lmax = fmaxf(lmax, fabsf(v));
    }

    if (slot_out >= 0) {
        for (int o = 16; o; o >>= 1) lmax = fmaxf(lmax, __shfl_xor_sync(0xffffffffu, lmax, o));
        if ((t & 31) == 0) redm[t >> 5] = lmax;
        __syncthreads();
        if (t < 8) {
            lmax = redm[t];
            for (int o = 4; o; o >>= 1) lmax = fmaxf(lmax, __shfl_xor_sync(0xffu, lmax, o));
            if (t == 0) atomicMax(&g_maxbits[slot_out], __float_as_int(lmax));
        }
    }
}

// ---------------------------------------------------------------------------
extern "C" void kernel_launch(void* const* d_in, const int* in_sizes, int n_in,
                              void* d_out, int out_size) {
    const float* x   = (const float*)d_in[0];
    const float* wp1 = (const float*)d_in[1];
    const float* wf1 = (const float*)d_in[2];
    const float* wp2 = (const float*)d_in[3];
    const float* wf2 = (const float*)d_in[4];
    const float* a1  = (const float*)d_in[5];
    const float* a2  = (const float*)d_in[6];
    float* out = (float*)d_out;

    float *bufA, *bufB, *qp1, *qf1, *qp2, *qf2;
    cudaGetSymbolAddress((void**)&bufA, g_bufA);
    cudaGetSymbolAddress((void**)&bufB, g_bufB);
    cudaGetSymbolAddress((void**)&qp1, g_wq_p1);
    cudaGetSymbolAddress((void**)&qf1, g_wq_f1);
    cudaGetSymbolAddress((void**)&qp2, g_wq_p2);
    cudaGetSymbolAddress((void**)&qf2, g_wq_f2);

    prep_kernel<<<1, 256>>>(wp1, wf1, wp2, wf2);
    kmax_x<<<2048, 256>>>(x);
    // y1 = conv1x1(fq(x), wq_p1)                      -> bufA, max -> slot1
    conv1x1_kernel<<<dim3(512, 16), 256>>>(x, bufA, qp1, 0, 1);
    // y2 = prelu(dw3x3(fq(y1), wq_f1), a1)            -> bufB, max -> slot2
    dwconv_kernel<<<dim3(64, 64, 16), 256>>>(bufA, bufB, qf1, a1, nullptr, 1, 2);
    // y3 = conv1x1(fq(y2), wq_p2)                     -> bufA, max -> slot3
    conv1x1_kernel<<<dim3(512, 16), 256>>>(bufB, bufA, qp2, 2, 3);
    // out = prelu(dw3x3(fq(y3), wq_f2), a2) + x       -> d_out
    dwconv_kernel<<<dim3(64, 64, 16), 256>>>(bufA, out, qf2, a2, x, 3, -1);
}

// round 3
// speedup vs baseline: 1.8053x; 1.8053x over previous
#include <cuda_runtime.h>
#include <cstddef>

#define W_    256
#define HW_   65536
#define C_    64
#define B_    16
#define NTOT_ (B_ * C_ * HW_)   // 67108864

// Scratch (allocation-free contract: __device__ globals)
__device__ float g_bufA[NTOT_];
__device__ float g_bufB[NTOT_];
__device__ int   g_maxbits[4];        // max|x|, max|y1|, max|y2|, max|y3| as float bits
__device__ float g_wsc[2];            // weight scales for p1, p2
__device__ int   g_wpack1[C_ * 16];   // [co][k4] packed int8x4 weights, conv p1
__device__ int   g_wpack2[C_ * 16];   // [co][k4] packed int8x4 weights, conv p2
__device__ float g_wq_f1[C_ * 9];     // dequantized depthwise weights
__device__ float g_wq_f2[C_ * 9];

// ---------------------------------------------------------------------------
// Prep: zero activation-max slots, quantize all weights (4-bit).
// Pointwise weights -> packed int8x4 [co][k4]; depthwise -> dequantized fp32.
// ---------------------------------------------------------------------------
__device__ float block_amax(const float* __restrict__ src, int n, float* red, int t) {
    float m = 0.f;
    for (int i = t; i < n; i += 256) m = fmaxf(m, fabsf(src[i]));
    red[t] = m;
    __syncthreads();
    for (int s = 128; s > 0; s >>= 1) {
        if (t < s) red[t] = fmaxf(red[t], red[t + s]);
        __syncthreads();
    }
    float r = red[0];
    __syncthreads();
    return r;
}

__device__ __forceinline__ int clamp7(int q) { return max(-7, min(7, q)); }

__global__ void prep_kernel(const float* __restrict__ wp1, const float* __restrict__ wf1,
                            const float* __restrict__ wp2, const float* __restrict__ wf2) {
    __shared__ float red[256];
    int t = threadIdx.x;
    if (t < 4) g_maxbits[t] = 0;

    // ---- p1 ----
    {
        float m = block_amax(wp1, C_ * C_, red, t);
        float sw = m / 7.0f + 1e-12f;
        float inv = 1.0f / sw;
        if (t == 0) g_wsc[0] = sw;
        for (int i = t; i < C_ * 16; i += 256) {
            int co = i >> 4, k4 = i & 15;
            int q[4];
            #pragma unroll
            for (int j = 0; j < 4; j++)
                q[j] = clamp7(__float2int_rn(wp1[co * 64 + k4 * 4 + j] * inv));
            g_wpack1[co * 16 + k4] =
                (int)__byte_perm(__byte_perm((unsigned)q[0], (unsigned)q[1], 0x0040),
                                 __byte_perm((unsigned)q[2], (unsigned)q[3], 0x0040), 0x5410);
        }
    }
    // ---- f1 ----
    {
        float m = block_amax(wf1, C_ * 9, red, t);
        float sw = m / 7.0f + 1e-12f;
        float inv = 1.0f / sw;
        for (int i = t; i < C_ * 9; i += 256)
            g_wq_f1[i] = (float)clamp7(__float2int_rn(wf1[i] * inv)) * sw;
    }
    // ---- p2 ----
    {
        float m = block_amax(wp2, C_ * C_, red, t);
        float sw = m / 7.0f + 1e-12f;
        float inv = 1.0f / sw;
        if (t == 0) g_wsc[1] = sw;
        for (int i = t; i < C_ * 16; i += 256) {
            int co = i >> 4, k4 = i & 15;
            int q[4];
            #pragma unroll
            for (int j = 0; j < 4; j++)
                q[j] = clamp7(__float2int_rn(wp2[co * 64 + k4 * 4 + j] * inv));
            g_wpack2[co * 16 + k4] =
                (int)__byte_perm(__byte_perm((unsigned)q[0], (unsigned)q[1], 0x0040),
                                 __byte_perm((unsigned)q[2], (unsigned)q[3], 0x0040), 0x5410);
        }
    }
    // ---- f2 ----
    {
        float m = block_amax(wf2, C_ * 9, red, t);
        float sw = m / 7.0f + 1e-12f;
        float inv = 1.0f / sw;
        for (int i = t; i < C_ * 9; i += 256)
            g_wq_f2[i] = (float)clamp7(__float2int_rn(wf2[i] * inv)) * sw;
    }
}

// ---------------------------------------------------------------------------
// Global max|x| reduction (slot 0)
// ---------------------------------------------------------------------------
__global__ void __launch_bounds__(256) kmax_x(const float* __restrict__ x) {
    float m = 0.f;
    const float4* x4 = (const float4*)x;
    size_t stride = (size_t)gridDim.x * blockDim.x;
    for (size_t i = (size_t)blockIdx.x * blockDim.x + threadIdx.x; i < NTOT_ / 4; i += stride) {
        float4 v = x4[i];
        m = fmaxf(m, fmaxf(fmaxf(fabsf(v.x), fabsf(v.y)), fmaxf(fabsf(v.z), fabsf(v.w))));
    }
    for (int o = 16; o; o >>= 1) m = fmaxf(m, __shfl_xor_sync(0xffffffffu, m, o));
    __shared__ float red[8];
    if ((threadIdx.x & 31) == 0) red[threadIdx.x >> 5] = m;
    __syncthreads();
    if (threadIdx.x < 8) {
        m = red[threadIdx.x];
        for (int o = 4; o; o >>= 1) m = fmaxf(m, __shfl_xor_sync(0xffu, m, o));
        if (threadIdx.x == 0) atomicMax(&g_maxbits[0], __float_as_int(m));
    }
}

// ---------------------------------------------------------------------------
// 1x1 conv as exact int8 GEMM via dp4a.
// Block: 128 pixels x all 64 cout, 256 threads. Thread: 1 pixel x 32 cout.
// Activations quantized on load (int8, +-127); accumulate exact int32;
// epilogue scales by s_act*s_w; output |max| tracked as integer max.
// ---------------------------------------------------------------------------
__global__ void __launch_bounds__(256)
conv1x1_kernel(const float* __restrict__ in, float* __restrict__ out,
               const int* __restrict__ wpack, int widx, int slot_in, int slot_out) {
    int t    = threadIdx.x;
    int tile = blockIdx.x;           // 0..511
    int b    = blockIdx.y;           // 0..15
    int p    = t & 127;              // pixel within tile
    int h    = t >> 7;               // cout half: 0 -> co 0..31, 1 -> co 32..63

    float sa  = __int_as_float(g_maxbits[slot_in]) / 127.0f + 1e-12f;
    float inv = 1.0f / sa;

    // Load + quantize + pack 64 cin values for this pixel (coalesced LDG32)
    const float* src = in + (size_t)b * C_ * HW_ + tile * 128 + p;
    int xq[16];
    #pragma unroll
    for (int k = 0; k < 16; k++) {
        int q[4];
        #pragma unroll
        for (int j = 0; j < 4; j++) {
            float v = src[(size_t)(4 * k + j) * HW_];
            int qi = __float2int_rn(v * inv);
            q[j] = max(-127, min(127, qi));
        }
        xq[k] = (int)__byte_perm(__byte_perm((unsigned)q[0], (unsigned)q[1], 0x0040),
                                 __byte_perm((unsigned)q[2], (unsigned)q[3], 0x0040), 0x5410);
    }

    // GEMM: 32 couts x 16 dp4a each; weights broadcast from L1/L2
    const int4* wp = (const int4*)wpack + (size_t)h * 32 * 4;   // 4 int4 per cout
    int acc[32];
    #pragma unroll
    for (int j = 0; j < 32; j++) {
        int4 w0 = __ldg(&wp[j * 4 + 0]);
        int4 w1 = __ldg(&wp[j * 4 + 1]);
        int4 w2 = __ldg(&wp[j * 4 + 2]);
        int4 w3 = __ldg(&wp[j * 4 + 3]);
        int a = 0;
        a = __dp4a(xq[0],  w0.x, a); a = __dp4a(xq[1],  w0.y, a);
        a = __dp4a(xq[2],  w0.z, a); a = __dp4a(xq[3],  w0.w, a);
        a = __dp4a(xq[4],  w1.x, a); a = __dp4a(xq[5],  w1.y, a);
        a = __dp4a(xq[6],  w1.z, a); a = __dp4a(xq[7],  w1.w, a);
        a = __dp4a(xq[8],  w2.x, a); a = __dp4a(xq[9],  w2.y, a);
        a = __dp4a(xq[10], w2.z, a); a = __dp4a(xq[11], w2.w, a);
        a = __dp4a(xq[12], w3.x, a); a = __dp4a(xq[13], w3.y, a);
        a = __dp4a(xq[14], w3.z, a); a = __dp4a(xq[15], w3.w, a);
        acc[j] = a;
    }

    float f = sa * g_wsc[widx];
    int amax = 0;
    float* dst = out + (size_t)b * C_ * HW_ + (size_t)(h * 32) * HW_ + tile * 128 + p;
    #pragma unroll
    for (int j = 0; j < 32; j++) {
        amax = max(amax, abs(acc[j]));
        dst[(size_t)j * HW_] = (float)acc[j] * f;
    }

    // block-level max -> single atomic
    for (int o = 16; o; o >>= 1) amax = max(amax, __shfl_xor_sync(0xffffffffu, amax, o));
    __shared__ int redm[8];
    if ((t & 31) == 0) redm[t >> 5] = amax;
    __syncthreads();
    if (t < 8) {
        amax = redm[t];
        for (int o = 4; o; o >>= 1) amax = max(amax, __shfl_xor_sync(0xffu, amax, o));
        if (t == 0) atomicMax(&g_maxbits[slot_out], __float_as_int((float)amax * f));
    }
}

// ---------------------------------------------------------------------------
// Depthwise 3x3 (pad 1) + PReLU (+ optional residual) + optional out-max.
// Block: 64x32 output tile of one (b,c) plane; 256 threads; thread = 8 outputs.
// ---------------------------------------------------------------------------
__global__ void __launch_bounds__(256)
dwconv_kernel(const float* __restrict__ in, float* __restrict__ out,
              const float* __restrict__ wq, const float* __restrict__ alpha,
              const float* __restrict__ residual,
              int slot_in, int slot_out) {
    __shared__ float tile[34 * 68];
    __shared__ float redm[8];

    int t  = threadIdx.x;
    int bx = blockIdx.x;          // 0..31 : 4 x-tiles(64 wide) x 8 y-tiles(32 high)
    int c  = blockIdx.y;
    int b  = blockIdx.z;
    int tx0 = (bx & 3) << 6;
    int ty0 = (bx >> 2) << 5;

    float s   = __int_as_float(g_maxbits[slot_in]) / 127.0f + 1e-12f;
    float inv = 1.0f / s;
    const float* base = in + ((size_t)(b * C_ + c)) * HW_;

    // Halo load 34 rows x 66 cols, quantize. 8 threads/row, 9 cols each.
    {
        int r0 = t >> 3;
        int c0 = (t & 7) * 9;
        for (int r = r0; r < 34; r += 32) {
            int gy = ty0 + r - 1;
            bool yok = (gy >= 0) & (gy < W_);
            const float* rowp = base + (size_t)gy * W_;
            #pragma unroll
            for (int k = 0; k < 9; k++) {
                int cc = c0 + k;
                if (cc < 66) {
                    int gx = tx0 + cc - 1;
                    float v = 0.f;
                    if (yok && gx >= 0 && gx < W_) v = rowp[gx];
                    tile[r * 68 + cc] = fminf(fmaxf(rintf(v * inv), -127.f), 127.f) * s;
                }
            }
        }
    }
    __syncthreads();

    float w[9];
    #pragma unroll
    for (int k = 0; k < 9; k++) w[k] = wq[c * 9 + k];
    float a = alpha[c];

    int r  = t >> 3;              // output row 0..31
    int cx = (t & 7) << 3;        // output col group, 8 wide
    float acc[8] = {0.f, 0.f, 0.f, 0.f, 0.f, 0.f, 0.f, 0.f};

    #pragma unroll
    for (int kh = 0; kh < 3; kh++) {
        const float* rp = &tile[(r + kh) * 68 + cx];
        float4 v0 = *(const float4*)rp;
        float4 v1 = *(const float4*)(rp + 4);
        float2 v2 = *(const float2*)(rp + 8);
        float v[10] = {v0.x, v0.y, v0.z, v0.w, v1.x, v1.y, v1.z, v1.w, v2.x, v2.y};
        float w0 = w[kh * 3], w1 = w[kh * 3 + 1], w2 = w[kh * 3 + 2];
        #pragma unroll
        for (int j = 0; j < 8; j++)
            acc[j] += w0 * v[j] + w1 * v[j + 1] + w2 * v[j + 2];
    }

    size_t obase = ((size_t)(b * C_ + c)) * HW_ + (size_t)(ty0 + r) * W_ + tx0 + cx;
    float o8[8];
    #pragma unroll
    for (int j = 0; j < 8; j++) o8[j] = acc[j] > 0.f ? acc[j] : a * acc[j];
    if (residual) {
        float4 r0 = *(const float4*)(residual + obase);
        float4 r1 = *(const float4*)(residual + obase + 4);
        o8[0] += r0.x; o8[1] += r0.y; o8[2] += r0.z; o8[3] += r0.w;
        o8[4] += r1.x; o8[5] += r1.y; o8[6] += r1.z; o8[7] += r1.w;
    }
    float vmax = 0.f;
    #pragma unroll
    for (int j = 0; j < 8; j++) vmax = fmaxf(vmax, fabsf(o8[j]));
    *(float4*)(out + obase)     = make_float4(o8[0], o8[1], o8[2], o8[3]);
    *(float4*)(out + obase + 4) = make_float4(o8[4], o8[5], o8[6], o8[7]);

    if (slot_out >= 0) {
        for (int o = 16; o; o >>= 1) vmax = fmaxf(vmax, __shfl_xor_sync(0xffffffffu, vmax, o));
        if ((t & 31) == 0) redm[t >> 5] = vmax;
        __syncthreads();
        if (t < 8) {
            vmax = redm[t];
            for (int o = 4; o; o >>= 1) vmax = fmaxf(vmax, __shfl_xor_sync(0xffu, vmax, o));
            if (t == 0) atomicMax(&g_maxbits[slot_out], __float_as_int(vmax));
        }
    }
}

// ---------------------------------------------------------------------------
extern "C" void kernel_launch(void* const* d_in, const int* in_sizes, int n_in,
                              void* d_out, int out_size) {
    const float* x   = (const float*)d_in[0];
    const float* wp1 = (const float*)d_in[1];
    const float* wf1 = (const float*)d_in[2];
    const float* wp2 = (const float*)d_in[3];
    const float* wf2 = (const float*)d_in[4];
    const float* a1  = (const float*)d_in[5];
    const float* a2  = (const float*)d_in[6];
    float* out = (float*)d_out;

    float *bufA, *bufB, *qf1, *qf2;
    int *wpk1, *wpk2;
    cudaGetSymbolAddress((void**)&bufA, g_bufA);
    cudaGetSymbolAddress((void**)&bufB, g_bufB);
    cudaGetSymbolAddress((void**)&qf1,  g_wq_f1);
    cudaGetSymbolAddress((void**)&qf2,  g_wq_f2);
    cudaGetSymbolAddress((void**)&wpk1, g_wpack1);
    cudaGetSymbolAddress((void**)&wpk2, g_wpack2);

    prep_kernel<<<1, 256>>>(wp1, wf1, wp2, wf2);
    kmax_x<<<2048, 256>>>(x);
    // y1 = conv1x1(fq(x), wq_p1)                      -> bufA, max -> slot1
    conv1x1_kernel<<<dim3(512, 16), 256>>>(x, bufA, wpk1, 0, 0, 1);
    // y2 = prelu(dw3x3(fq(y1), wq_f1), a1)            -> bufB, max -> slot2
    dwconv_kernel<<<dim3(32, 64, 16), 256>>>(bufA, bufB, qf1, a1, nullptr, 1, 2);
    // y3 = conv1x1(fq(y2), wq_p2)                     -> bufA, max -> slot3
    conv1x1_kernel<<<dim3(512, 16), 256>>>(bufB, bufA, wpk2, 1, 2, 3);
    // out = prelu(dw3x3(fq(y3), wq_f2), a2) + x       -> d_out
    dwconv_kernel<<<dim3(32, 64, 16), 256>>>(bufA, out, qf2, a2, x, 3, -1);
}

// round 5
// speedup vs baseline: 2.2559x; 1.2496x over previous
#include <cuda_runtime.h>
#include <cstddef>

#define W_    256
#define HW_   65536
#define C_    64
#define B_    16
#define NTOT_ (B_ * C_ * HW_)   // 67108864

// Scratch (allocation-free contract: __device__ globals)
__device__ float g_bufA[NTOT_];
__device__ float g_bufB[NTOT_];
__device__ int   g_maxbits[4];        // max|x|, max|y1|, max|y2|, max|y3| as float bits
__device__ float g_wsc[2];            // weight scales for p1, p2
__device__ int   g_wpack1[C_ * 16];   // [co][k4] packed int8x4 weights, conv p1
__device__ int   g_wpack2[C_ * 16];   // [co][k4] packed int8x4 weights, conv p2
__device__ float g_wq_f1[C_ * 9];     // dequantized depthwise weights
__device__ float g_wq_f2[C_ * 9];

__device__ __forceinline__ int pack4(int a, int b, int c, int d) {
    return (int)__byte_perm(__byte_perm((unsigned)a, (unsigned)b, 0x0040),
                            __byte_perm((unsigned)c, (unsigned)d, 0x0040), 0x5410);
}

// ---------------------------------------------------------------------------
// Prep: zero activation-max slots, quantize all weights (4-bit).
// ---------------------------------------------------------------------------
__device__ float block_amax(const float* __restrict__ src, int n, float* red, int t) {
    float m = 0.f;
    for (int i = t; i < n; i += 256) m = fmaxf(m, fabsf(src[i]));
    red[t] = m;
    __syncthreads();
    for (int s = 128; s > 0; s >>= 1) {
        if (t < s) red[t] = fmaxf(red[t], red[t + s]);
        __syncthreads();
    }
    float r = red[0];
    __syncthreads();
    return r;
}

__device__ __forceinline__ int clamp7(int q) { return max(-7, min(7, q)); }

__global__ void prep_kernel(const float* __restrict__ wp1, const float* __restrict__ wf1,
                            const float* __restrict__ wp2, const float* __restrict__ wf2) {
    __shared__ float red[256];
    int t = threadIdx.x;
    if (t < 4) g_maxbits[t] = 0;

    {   // p1
        float m = block_amax(wp1, C_ * C_, red, t);
        float sw = m / 7.0f + 1e-12f;
        float inv = 1.0f / sw;
        if (t == 0) g_wsc[0] = sw;
        for (int i = t; i < C_ * 16; i += 256) {
            int co = i >> 4, k4 = i & 15;
            int q[4];
            #pragma unroll
            for (int j = 0; j < 4; j++)
                q[j] = clamp7(__float2int_rn(wp1[co * 64 + k4 * 4 + j] * inv));
            g_wpack1[co * 16 + k4] = pack4(q[0], q[1], q[2], q[3]);
        }
    }
    {   // f1
        float m = block_amax(wf1, C_ * 9, red, t);
        float sw = m / 7.0f + 1e-12f;
        float inv = 1.0f / sw;
        for (int i = t; i < C_ * 9; i += 256)
            g_wq_f1[i] = (float)clamp7(__float2int_rn(wf1[i] * inv)) * sw;
    }
    {   // p2
        float m = block_amax(wp2, C_ * C_, red, t);
        float sw = m / 7.0f + 1e-12f;
        float inv = 1.0f / sw;
        if (t == 0) g_wsc[1] = sw;
        for (int i = t; i < C_ * 16; i += 256) {
            int co = i >> 4, k4 = i & 15;
            int q[4];
            #pragma unroll
            for (int j = 0; j < 4; j++)
                q[j] = clamp7(__float2int_rn(wp2[co * 64 + k4 * 4 + j] * inv));
            g_wpack2[co * 16 + k4] = pack4(q[0], q[1], q[2], q[3]);
        }
    }
    {   // f2
        float m = block_amax(wf2, C_ * 9, red, t);
        float sw = m / 7.0f + 1e-12f;
        float inv = 1.0f / sw;
        for (int i = t; i < C_ * 9; i += 256)
            g_wq_f2[i] = (float)clamp7(__float2int_rn(wf2[i] * inv)) * sw;
    }
}

// ---------------------------------------------------------------------------
// Global max|x| reduction (slot 0)
// ---------------------------------------------------------------------------
__global__ void __launch_bounds__(256) kmax_x(const float* __restrict__ x) {
    float m = 0.f;
    const float4* x4 = (const float4*)x;
    size_t stride = (size_t)gridDim.x * blockDim.x;
    for (size_t i = (size_t)blockIdx.x * blockDim.x + threadIdx.x; i < NTOT_ / 4; i += stride) {
        float4 v = x4[i];
        m = fmaxf(m, fmaxf(fmaxf(fabsf(v.x), fabsf(v.y)), fmaxf(fabsf(v.z), fabsf(v.w))));
    }
    for (int o = 16; o; o >>= 1) m = fmaxf(m, __shfl_xor_sync(0xffffffffu, m, o));
    __shared__ float red[8];
    if ((threadIdx.x & 31) == 0) red[threadIdx.x >> 5] = m;
    __syncthreads();
    if (threadIdx.x < 8) {
        m = red[threadIdx.x];
        for (int o = 4; o; o >>= 1) m = fmaxf(m, __shfl_xor_sync(0xffu, m, o));
        if (threadIdx.x == 0) atomicMax(&g_maxbits[0], __float_as_int(m));
    }
}

// ---------------------------------------------------------------------------
// 1x1 conv as exact int8 GEMM via dp4a, SMEM-staged packed activations.
// Block: 128-pixel tile, 256 threads. Stage: quantize+pack tile once into
// xsq[k4][pixel]. Compute: thread = 1 pixel x 32 couts (two halves).
// No clamps needed: scale slots are exact tensor maxima -> |q| <= 127 always.
// ---------------------------------------------------------------------------
__global__ void __launch_bounds__(256)
conv1x1_kernel(const float* __restrict__ in, float* __restrict__ out,
               const int* __restrict__ wpack, int widx, int slot_in, int slot_out) {
    __shared__ int xsq[16][132];   // [k4][pixel], padded
    __shared__ int redm[8];

    int t    = threadIdx.x;
    int tile = blockIdx.x;           // 0..511
    int b    = blockIdx.y;           // 0..15

    float sa  = __int_as_float(g_maxbits[slot_in]) / 127.0f + 1e-12f;
    float inv = 1.0f / sa;

    // Stage phase: thread (px4 = t&31, kq = t>>5) loads 4 cin-rows x 4 pixels,
    // quantizes, transposes into per-pixel packed int8x4, STS.128.
    const float* src = in + (size_t)b * C_ * HW_ + tile * 128;
    int px4 = t & 31;
    int kq  = t >> 5;
    #pragma unroll
    for (int it = 0; it < 2; it++) {
        int k4 = kq + it * 8;
        int q[4][4];
        #pragma unroll
        for (int r = 0; r < 4; r++) {
            float4 v = *(const float4*)(src + (size_t)(k4 * 4 + r) * HW_ + px4 * 4);
            q[r][0] = __float2int_rn(v.x * inv);
            q[r][1] = __float2int_rn(v.y * inv);
            q[r][2] = __float2int_rn(v.z * inv);
            q[r][3] = __float2int_rn(v.w * inv);
        }
        int4 pk;
        pk.x = pack4(q[0][0], q[1][0], q[2][0], q[3][0]);
        pk.y = pack4(q[0][1], q[1][1], q[2][1], q[3][1]);
        pk.z = pack4(q[0][2], q[1][2], q[2][2], q[3][2]);
        pk.w = pack4(q[0][3], q[1][3], q[2][3], q[3][3]);
        *(int4*)&xsq[k4][px4 * 4] = pk;
    }
    __syncthreads();

    int p = t & 127;                 // pixel
    int h = t >> 7;                  // cout half
    int xq[16];
    #pragma unroll
    for (int i = 0; i < 16; i++) xq[i] = xsq[i][p];

    const int4* wp = (const int4*)wpack + (size_t)h * 32 * 4;
    int acc[32];
    #pragma unroll
    for (int j = 0; j < 32; j++) {
        int4 w0 = __ldg(&wp[j * 4 + 0]);
        int4 w1 = __ldg(&wp[j * 4 + 1]);
        int4 w2 = __ldg(&wp[j * 4 + 2]);
        int4 w3 = __ldg(&wp[j * 4 + 3]);
        int a = 0;
        a = __dp4a(xq[0],  w0.x, a); a = __dp4a(xq[1],  w0.y, a);
        a = __dp4a(xq[2],  w0.z, a); a = __dp4a(xq[3],  w0.w, a);
        a = __dp4a(xq[4],  w1.x, a); a = __dp4a(xq[5],  w1.y, a);
        a = __dp4a(xq[6],  w1.z, a); a = __dp4a(xq[7],  w1.w, a);
        a = __dp4a(xq[8],  w2.x, a); a = __dp4a(xq[9],  w2.y, a);
        a = __dp4a(xq[10], w2.z, a); a = __dp4a(xq[11], w2.w, a);
        a = __dp4a(xq[12], w3.x, a); a = __dp4a(xq[13], w3.y, a);
        a = __dp4a(xq[14], w3.z, a); a = __dp4a(xq[15], w3.w, a);
        acc[j] = a;
    }

    float f = sa * g_wsc[widx];
    int amax = 0;
    float* dst = out + (size_t)b * C_ * HW_ + (size_t)(h * 32) * HW_ + tile * 128 + p;
    #pragma unroll
    for (int j = 0; j < 32; j++) {
        amax = max(amax, abs(acc[j]));
        dst[(size_t)j * HW_] = (float)acc[j] * f;
    }

    for (int o = 16; o; o >>= 1) amax = max(amax, __shfl_xor_sync(0xffffffffu, amax, o));
    if ((t & 31) == 0) redm[t >> 5] = amax;
    __syncthreads();
    if (t < 8) {
        amax = redm[t];
        for (int o = 4; o; o >>= 1) amax = max(amax, __shfl_xor_sync(0xffu, amax, o));
        if (t == 0) atomicMax(&g_maxbits[slot_out], __float_as_int((float)amax * f));
    }
}

// ---------------------------------------------------------------------------
// Depthwise 3x3 (pad 1) + PReLU (+ optional residual) + optional out-max.
// No shared memory: one warp = one full 256-wide row (lane = 8 cols),
// cross-lane neighbors via shuffle, sliding 3-row register window, 32 rows/warp.
// ---------------------------------------------------------------------------
__device__ __forceinline__ void load_qrow(const float* __restrict__ base, int gy, int x0,
                                          float s, float inv, int lane, float (&d)[10]) {
    if (gy < 0 || gy >= W_) {          // warp-uniform branch (gy same for all lanes)
        #pragma unroll
        for (int j = 0; j < 10; j++) d[j] = 0.f;
        return;
    }
    const float* rp = base + (size_t)gy * W_ + x0;
    float4 v0 = *(const float4*)rp;
    float4 v1 = *(const float4*)(rp + 4);
    float q[8];
    q[0] = rintf(v0.x * inv) * s; q[1] = rintf(v0.y * inv) * s;
    q[2] = rintf(v0.z * inv) * s; q[3] = rintf(v0.w * inv) * s;
    q[4] = rintf(v1.x * inv) * s; q[5] = rintf(v1.y * inv) * s;
    q[6] = rintf(v1.z * inv) * s; q[7] = rintf(v1.w * inv) * s;
    float left  = __shfl_up_sync(0xffffffffu, q[7], 1);
    float right = __shfl_down_sync(0xffffffffu, q[0], 1);
    d[0] = (lane == 0)  ? 0.f : left;
    d[9] = (lane == 31) ? 0.f : right;
    #pragma unroll
    for (int j = 0; j < 8; j++) d[j + 1] = q[j];
}

__device__ __forceinline__ void dw_row(const float (&rm)[10], const float (&rc)[10],
                                       const float (&rp)[10], const float* w, float a,
                                       const float* __restrict__ res, float* __restrict__ outp,
                                       float& vmax) {
    float acc[8];
    #pragma unroll
    for (int j = 0; j < 8; j++)
        acc[j] = w[0] * rm[j] + w[1] * rm[j + 1] + w[2] * rm[j + 2]
               + w[3] * rc[j] + w[4] * rc[j + 1] + w[5] * rc[j + 2]
               + w[6] * rp[j] + w[7] * rp[j + 1] + w[8] * rp[j + 2];
    float o8[8];
    #pragma unroll
    for (int j = 0; j < 8; j++) o8[j] = acc[j] > 0.f ? acc[j] : a * acc[j];
    if (res) {
        float4 r0 = *(const float4*)res;
        float4 r1 = *(const float4*)(res + 4);
        o8[0] += r0.x; o8[1] += r0.y; o8[2] += r0.z; o8[3] += r0.w;
        o8[4] += r1.x; o8[5] += r1.y; o8[6] += r1.z; o8[7] += r1.w;
    }
    #pragma unroll
    for (int j = 0; j < 8; j++) vmax = fmaxf(vmax, fabsf(o8[j]));
    *(float4*)outp       = make_float4(o8[0], o8[1], o8[2], o8[3]);
    *(float4*)(outp + 4) = make_float4(o8[4], o8[5], o8[6], o8[7]);
}

__global__ void __launch_bounds__(256)
dwconv_kernel(const float* __restrict__ in, float* __restrict__ out,
              const float* __restrict__ wq, const float* __restrict__ alpha,
              const float* __restrict__ residual,
              int slot_in, int slot_out) {
    __shared__ float redm[8];
    int t    = threadIdx.x;
    int lane = t & 31;
    int warp = t >> 5;               // 0..7: rows [warp*32, warp*32+32)
    int c = blockIdx.x;
    int b = blockIdx.y;

    float s   = __int_as_float(g_maxbits[slot_in]) / 127.0f + 1e-12f;
    float inv = 1.0f / s;

    size_t plane = (size_t)(b * C_ + c) * HW_;
    const float* base = in + plane;
    float* outbase = out + plane;
    const float* resbase = residual ? residual + plane : nullptr;

    float w[9];
    #pragma unroll
    for (int k = 0; k < 9; k++) w[k] = wq[c * 9 + k];
    float a = alpha[c];

    int x0   = lane * 8;
    int row0 = warp * 32;

    float rows[3][10];
    load_qrow(base, row0 - 1, x0, s, inv, lane, rows[0]);
    load_qrow(base, row0,     x0, s, inv, lane, rows[1]);

    float vmax = 0.f;

#define DW_STEP(I, RM, RC, RP)                                                   \
    {                                                                            \
        load_qrow(base, row0 + (I) + 1, x0, s, inv, lane, rows[RP]);             \
        size_t off = (size_t)(row0 + (I)) * W_ + x0;                             \
        dw_row(rows[RM], rows[RC], rows[RP], w, a,                               \
               resbase ? resbase + off : nullptr, outbase + off, vmax);          \
    }

    #pragma unroll 1
    for (int i = 0; i < 30; i += 3) {
        DW_STEP(i + 0, 0, 1, 2)
        DW_STEP(i + 1, 1, 2, 0)
        DW_STEP(i + 2, 2, 0, 1)
    }
    DW_STEP(30, 0, 1, 2)
    DW_STEP(31, 1, 2, 0)
#undef DW_STEP

    if (slot_out >= 0) {
        for (int o = 16; o; o >>= 1) vmax = fmaxf(vmax, __shfl_xor_sync(0xffffffffu, vmax, o));
        if ((t & 31) == 0) redm[t >> 5] = vmax;
        __syncthreads();
        if (t < 8) {
            vmax = redm[t];
            for (int o = 4; o; o >>= 1) vmax = fmaxf(vmax, __shfl_xor_sync(0xffu, vmax, o));
            if (t == 0) atomicMax(&g_maxbits[slot_out], __float_as_int(vmax));
        }
    }
}

// ---------------------------------------------------------------------------
extern "C" void kernel_launch(void* const* d_in, const int* in_sizes, int n_in,
                              void* d_out, int out_size) {
    const float* x   = (const float*)d_in[0];
    const float* wp1 = (const float*)d_in[1];
    const float* wf1 = (const float*)d_in[2];
    const float* wp2 = (const float*)d_in[3];
    const float* wf2 = (const float*)d_in[4];
    const float* a1  = (const float*)d_in[5];
    const float* a2  = (const float*)d_in[6];
    float* out = (float*)d_out;

    float *bufA, *bufB, *qf1, *qf2;
    int *wpk1, *wpk2;
    cudaGetSymbolAddress((void**)&bufA, g_bufA);
    cudaGetSymbolAddress((void**)&bufB, g_bufB);
    cudaGetSymbolAddress((void**)&qf1,  g_wq_f1);
    cudaGetSymbolAddress((void**)&qf2,  g_wq_f2);
    cudaGetSymbolAddress((void**)&wpk1, g_wpack1);
    cudaGetSymbolAddress((void**)&wpk2, g_wpack2);

    prep_kernel<<<1, 256>>>(wp1, wf1, wp2, wf2);
    kmax_x<<<2048, 256>>>(x);
    // y1 = conv1x1(fq(x), wq_p1)                      -> bufA, max -> slot1
    conv1x1_kernel<<<dim3(512, 16), 256>>>(x, bufA, wpk1, 0, 0, 1);
    // y2 = prelu(dw3x3(fq(y1), wq_f1), a1)            -> bufB, max -> slot2
    dwconv_kernel<<<dim3(64, 16), 256>>>(bufA, bufB, qf1, a1, nullptr, 1, 2);
    // y3 = conv1x1(fq(y2), wq_p2)                     -> bufA, max -> slot3
    conv1x1_kernel<<<dim3(512, 16), 256>>>(bufB, bufA, wpk2, 1, 2, 3);
    // out = prelu(dw3x3(fq(y3), wq_f2), a2) + x       -> d_out
    dwconv_kernel<<<dim3(64, 16), 256>>>(bufA, out, qf2, a2, x, 3, -1);
}

// round 7
// speedup vs baseline: 3.0177x; 1.3377x over previous
#include <cuda_runtime.h>
#include <cstddef>

#define W_    256
#define HW_   65536
#define C_    64
#define B_    16
#define NTOT_ (B_ * C_ * HW_)   // 67108864

// Scratch (allocation-free contract: __device__ globals)
__device__ float g_bufA[NTOT_];
__device__ float g_bufB[NTOT_];
__device__ int   g_maxbits[4];        // max|x|, max|y1|, max|y2|, max|y3| as float bits
__device__ float g_wsc[2];            // weight scales for p1, p2
__device__ int   g_wpack1[C_ * 16];   // [co][k4] packed int8x4 weights, conv p1
__device__ int   g_wpack2[C_ * 16];   // [co][k4] packed int8x4 weights, conv p2
__device__ float g_wq_f1[C_ * 9];     // dequantized depthwise weights
__device__ float g_wq_f2[C_ * 9];

__device__ __forceinline__ int pack4(int a, int b, int c, int d) {
    return (int)__byte_perm(__byte_perm((unsigned)a, (unsigned)b, 0x0040),
                            __byte_perm((unsigned)c, (unsigned)d, 0x0040), 0x5410);
}

// ---------------------------------------------------------------------------
// Prep: zero activation-max slots, quantize all weights (4-bit).
// ---------------------------------------------------------------------------
__device__ float block_amax(const float* __restrict__ src, int n, float* red, int t) {
    float m = 0.f;
    for (int i = t; i < n; i += 256) m = fmaxf(m, fabsf(src[i]));
    red[t] = m;
    __syncthreads();
    for (int s = 128; s > 0; s >>= 1) {
        if (t < s) red[t] = fmaxf(red[t], red[t + s]);
        __syncthreads();
    }
    float r = red[0];
    __syncthreads();
    return r;
}

__device__ __forceinline__ int clamp7(int q) { return max(-7, min(7, q)); }

__global__ void prep_kernel(const float* __restrict__ wp1, const float* __restrict__ wf1,
                            const float* __restrict__ wp2, const float* __restrict__ wf2) {
    __shared__ float red[256];
    int t = threadIdx.x;
    if (t < 4) g_maxbits[t] = 0;

    {   // p1
        float m = block_amax(wp1, C_ * C_, red, t);
        float sw = m / 7.0f + 1e-12f;
        float inv = 1.0f / sw;
        if (t == 0) g_wsc[0] = sw;
        for (int i = t; i < C_ * 16; i += 256) {
            int co = i >> 4, k4 = i & 15;
            int q[4];
            #pragma unroll
            for (int j = 0; j < 4; j++)
                q[j] = clamp7(__float2int_rn(wp1[co * 64 + k4 * 4 + j] * inv));
            g_wpack1[co * 16 + k4] = pack4(q[0], q[1], q[2], q[3]);
        }
    }
    {   // f1
        float m = block_amax(wf1, C_ * 9, red, t);
        float sw = m / 7.0f + 1e-12f;
        float inv = 1.0f / sw;
        for (int i = t; i < C_ * 9; i += 256)
            g_wq_f1[i] = (float)clamp7(__float2int_rn(wf1[i] * inv)) * sw;
    }
    {   // p2
        float m = block_amax(wp2, C_ * C_, red, t);
        float sw = m / 7.0f + 1e-12f;
        float inv = 1.0f / sw;
        if (t == 0) g_wsc[1] = sw;
        for (int i = t; i < C_ * 16; i += 256) {
            int co = i >> 4, k4 = i & 15;
            int q[4];
            #pragma unroll
            for (int j = 0; j < 4; j++)
                q[j] = clamp7(__float2int_rn(wp2[co * 64 + k4 * 4 + j] * inv));
            g_wpack2[co * 16 + k4] = pack4(q[0], q[1], q[2], q[3]);
        }
    }
    {   // f2
        float m = block_amax(wf2, C_ * 9, red, t);
        float sw = m / 7.0f + 1e-12f;
        float inv = 1.0f / sw;
        for (int i = t; i < C_ * 9; i += 256)
            g_wq_f2[i] = (float)clamp7(__float2int_rn(wf2[i] * inv)) * sw;
    }
}

// Separator so ncu's fixed -s 5 lands on a conv1x1 launch next round.
__global__ void noop_kernel() {}

// ---------------------------------------------------------------------------
// Global max|x| reduction (slot 0)
// ---------------------------------------------------------------------------
__global__ void __launch_bounds__(256) kmax_x(const float* __restrict__ x) {
    float m = 0.f;
    const float4* x4 = (const float4*)x;
    size_t stride = (size_t)gridDim.x * blockDim.x;
    for (size_t i = (size_t)blockIdx.x * blockDim.x + threadIdx.x; i < NTOT_ / 4; i += stride) {
        float4 v = x4[i];
        m = fmaxf(m, fmaxf(fmaxf(fabsf(v.x), fabsf(v.y)), fmaxf(fabsf(v.z), fabsf(v.w))));
    }
    for (int o = 16; o; o >>= 1) m = fmaxf(m, __shfl_xor_sync(0xffffffffu, m, o));
    __shared__ float red[8];
    if ((threadIdx.x & 31) == 0) red[threadIdx.x >> 5] = m;
    __syncthreads();
    if (threadIdx.x < 8) {
        m = red[threadIdx.x];
        for (int o = 4; o; o >>= 1) m = fmaxf(m, __shfl_xor_sync(0xffu, m, o));
        if (threadIdx.x == 0) atomicMax(&g_maxbits[0], __float_as_int(m));
    }
}

// ---------------------------------------------------------------------------
// 1x1 conv as exact int8 GEMM via dp4a.
// SMEM-staged packed activations AND weights; couts in two passes of 16 to
// cap live registers (acc[16]) and raise occupancy.
// No clamps needed: scale slots are exact tensor maxima -> |q| <= 127 always.
// ---------------------------------------------------------------------------
__global__ void __launch_bounds__(256)
conv1x1_kernel(const float* __restrict__ in, float* __restrict__ out,
               const int* __restrict__ wpack, int widx, int slot_in, int slot_out) {
    __shared__ int  xsq[16][132];    // [k4][pixel], padded
    __shared__ int4 wsh[256];        // [co][k4quad]: 64 couts x 4 int4
    __shared__ int  redm[8];

    int t    = threadIdx.x;
    int tile = blockIdx.x;           // 0..511
    int b    = blockIdx.y;           // 0..15

    float sa  = __int_as_float(g_maxbits[slot_in]) / 127.0f + 1e-12f;
    float inv = 1.0f / sa;

    // Weights -> SMEM (1 KB)
    wsh[t] = ((const int4*)wpack)[t];

    // Stage: thread (px4 = t&31, kq = t>>5) loads 4 cin-rows x 4 pixels,
    // quantizes, transposes into per-pixel packed int8x4, STS.128.
    const float* src = in + (size_t)b * C_ * HW_ + tile * 128;
    int px4 = t & 31;
    int kq  = t >> 5;
    #pragma unroll
    for (int it = 0; it < 2; it++) {
        int k4 = kq + it * 8;
        int q[4][4];
        #pragma unroll
        for (int r = 0; r < 4; r++) {
            float4 v = *(const float4*)(src + (size_t)(k4 * 4 + r) * HW_ + px4 * 4);
            q[r][0] = __float2int_rn(v.x * inv);
            q[r][1] = __float2int_rn(v.y * inv);
            q[r][2] = __float2int_rn(v.z * inv);
            q[r][3] = __float2int_rn(v.w * inv);
        }
        int4 pk;
        pk.x = pack4(q[0][0], q[1][0], q[2][0], q[3][0]);
        pk.y = pack4(q[0][1], q[1][1], q[2][1], q[3][1]);
        pk.z = pack4(q[0][2], q[1][2], q[2][2], q[3][2]);
        pk.w = pack4(q[0][3], q[1][3], q[2][3], q[3][3]);
        *(int4*)&xsq[k4][px4 * 4] = pk;
    }
    __syncthreads();

    int p = t & 127;                 // pixel
    int h = t >> 7;                  // cout half
    int xq[16];
    #pragma unroll
    for (int i = 0; i < 16; i++) xq[i] = xsq[i][p];

    float f = sa * g_wsc[widx];
    int amax = 0;
    float* dst = out + (size_t)b * C_ * HW_ + (size_t)(h * 32) * HW_ + tile * 128 + p;

    #pragma unroll
    for (int pass = 0; pass < 2; pass++) {
        int cbase = h * 32 + pass * 16;
        int acc[16];
        #pragma unroll
        for (int j = 0; j < 16; j++) {
            const int4* wp = &wsh[(cbase + j) * 4];
            int4 w0 = wp[0], w1 = wp[1], w2 = wp[2], w3 = wp[3];
            int a = 0;
            a = __dp4a(xq[0],  w0.x, a); a = __dp4a(xq[1],  w0.y, a);
            a = __dp4a(xq[2],  w0.z, a); a = __dp4a(xq[3],  w0.w, a);
            a = __dp4a(xq[4],  w1.x, a); a = __dp4a(xq[5],  w1.y, a);
            a = __dp4a(xq[6],  w1.z, a); a = __dp4a(xq[7],  w1.w, a);
            a = __dp4a(xq[8],  w2.x, a); a = __dp4a(xq[9],  w2.y, a);
            a = __dp4a(xq[10], w2.z, a); a = __dp4a(xq[11], w2.w, a);
            a = __dp4a(xq[12], w3.x, a); a = __dp4a(xq[13], w3.y, a);
            a = __dp4a(xq[14], w3.z, a); a = __dp4a(xq[15], w3.w, a);
            acc[j] = a;
        }
        #pragma unroll
        for (int j = 0; j < 16; j++) {
            amax = max(amax, abs(acc[j]));
            dst[(size_t)(pass * 16 + j) * HW_] = (float)acc[j] * f;
        }
    }

    for (int o = 16; o; o >>= 1) amax = max(amax, __shfl_xor_sync(0xffffffffu, amax, o));
    if ((t & 31) == 0) redm[t >> 5] = amax;
    __syncthreads();
    if (t < 8) {
        amax = redm[t];
        for (int o = 4; o; o >>= 1) amax = max(amax, __shfl_xor_sync(0xffu, amax, o));
        if (t == 0) atomicMax(&g_maxbits[slot_out], __float_as_int((float)amax * f));
    }
}

// ---------------------------------------------------------------------------
// Depthwise 3x3 (pad 1) + PReLU (+ optional residual) + optional out-max.
// No shared memory: one warp = one full 256-wide row (lane = 8 cols),
// cross-lane neighbors via shuffle, sliding 3-row register window.
// 2 CTAs per plane, warp = 16 rows.
// ---------------------------------------------------------------------------
__device__ __forceinline__ void load_qrow(const float* __restrict__ base, int gy, int x0,
                                          float s, float inv, int lane, float (&d)[10]) {
    if (gy < 0 || gy >= W_) {          // warp-uniform branch
        #pragma unroll
        for (int j = 0; j < 10; j++) d[j] = 0.f;
        return;
    }
    const float* rp = base + (size_t)gy * W_ + x0;
    float4 v0 = *(const float4*)rp;
    float4 v1 = *(const float4*)(rp + 4);
    float q[8];
    q[0] = rintf(v0.x * inv) * s; q[1] = rintf(v0.y * inv) * s;
    q[2] = rintf(v0.z * inv) * s; q[3] = rintf(v0.w * inv) * s;
    q[4] = rintf(v1.x * inv) * s; q[5] = rintf(v1.y * inv) * s;
    q[6] = rintf(v1.z * inv) * s; q[7] = rintf(v1.w * inv) * s;
    float left  = __shfl_up_sync(0xffffffffu, q[7], 1);
    float right = __shfl_down_sync(0xffffffffu, q[0], 1);
    d[0] = (lane == 0)  ? 0.f : left;
    d[9] = (lane == 31) ? 0.f : right;
    #pragma unroll
    for (int j = 0; j < 8; j++) d[j + 1] = q[j];
}

__device__ __forceinline__ void dw_row(const float (&rm)[10], const float (&rc)[10],
                                       const float (&rp)[10], const float* w, float a,
                                       const float* __restrict__ res, float* __restrict__ outp,
                                       float& vmax) {
    float acc[8];
    #pragma unroll
    for (int j = 0; j < 8; j++)
        acc[j] = w[0] * rm[j] + w[1] * rm[j + 1] + w[2] * rm[j + 2]
               + w[3] * rc[j] + w[4] * rc[j + 1] + w[5] * rc[j + 2]
               + w[6] * rp[j] + w[7] * rp[j + 1] + w[8] * rp[j + 2];
    float o8[8];
    #pragma unroll
    for (int j = 0; j < 8; j++) o8[j] = acc[j] > 0.f ? acc[j] : a * acc[j];
    if (res) {
        float4 r0 = *(const float4*)res;
        float4 r1 = *(const float4*)(res + 4);
        o8[0] += r0.x; o8[1] += r0.y; o8[2] += r0.z; o8[3] += r0.w;
        o8[4] += r1.x; o8[5] += r1.y; o8[6] += r1.z; o8[7] += r1.w;
    }
    #pragma unroll
    for (int j = 0; j < 8; j++) vmax = fmaxf(vmax, fabsf(o8[j]));
    *(float4*)outp       = make_float4(o8[0], o8[1], o8[2], o8[3]);
    *(float4*)(outp + 4) = make_float4(o8[4], o8[5], o8[6], o8[7]);
}

__global__ void __launch_bounds__(256)
dwconv_kernel(const float* __restrict__ in, float* __restrict__ out,
              const float* __restrict__ wq, const float* __restrict__ alpha,
              const float* __restrict__ residual,
              int slot_in, int slot_out) {
    __shared__ float redm[8];
    int t    = threadIdx.x;
    int lane = t & 31;
    int warp = t >> 5;
    int c    = blockIdx.x >> 1;
    int half = blockIdx.x & 1;
    int b    = blockIdx.y;

    float s   = __int_as_float(g_maxbits[slot_in]) / 127.0f + 1e-12f;
    float inv = 1.0f / s;

    size_t plane = (size_t)(b * C_ + c) * HW_;
    const float* base = in + plane;
    float* outbase = out + plane;
    const float* resbase = residual ? residual + plane : nullptr;

    float w[9];
    #pragma unroll
    for (int k = 0; k < 9; k++) w[k] = wq[c * 9 + k];
    float a = alpha[c];

    int x0   = lane * 8;
    int row0 = half * 128 + warp * 16;

    float rows[3][10];
    load_qrow(base, row0 - 1, x0, s, inv, lane, rows[0]);
    load_qrow(base, row0,     x0, s, inv, lane, rows[1]);

    float vmax = 0.f;

#define DW_STEP(I, RM, RC, RP)                                                   \
    {                                                                            \
        load_qrow(base, row0 + (I) + 1, x0, s, inv, lane, rows[RP]);             \
        size_t off = (size_t)(row0 + (I)) * W_ + x0;                             \
        dw_row(rows[RM], rows[RC], rows[RP], w, a,                               \
               resbase ? resbase + off : nullptr, outbase + off, vmax);          \
    }

    #pragma unroll 1
    for (int i = 0; i < 15; i += 3) {
        DW_STEP(i + 0, 0, 1, 2)
        DW_STEP(i + 1, 1, 2, 0)
        DW_STEP(i + 2, 2, 0, 1)
    }
    DW_STEP(15, 0, 1, 2)
#undef DW_STEP

    if (slot_out >= 0) {
        for (int o = 16; o; o >>= 1) vmax = fmaxf(vmax, __shfl_xor_sync(0xffffffffu, vmax, o));
        if ((t & 31) == 0) redm[t >> 5] = vmax;
        __syncthreads();
        if (t < 8) {
            vmax = redm[t];
            for (int o = 4; o; o >>= 1) vmax = fmaxf(vmax, __shfl_xor_sync(0xffu, vmax, o));
            if (t == 0) atomicMax(&g_maxbits[slot_out], __float_as_int(vmax));
        }
    }
}

// ---------------------------------------------------------------------------
extern "C" void kernel_launch(void* const* d_in, const int* in_sizes, int n_in,
                              void* d_out, int out_size) {
    const float* x   = (const float*)d_in[0];
    const float* wp1 = (const float*)d_in[1];
    const float* wf1 = (const float*)d_in[2];
    const float* wp2 = (const float*)d_in[3];
    const float* wf2 = (const float*)d_in[4];
    const float* a1  = (const float*)d_in[5];
    const float* a2  = (const float*)d_in[6];
    float* out = (float*)d_out;

    float *bufA, *bufB, *qf1, *qf2;
    int *wpk1, *wpk2;
    cudaGetSymbolAddress((void**)&bufA, g_bufA);
    cudaGetSymbolAddress((void**)&bufB, g_bufB);
    cudaGetSymbolAddress((void**)&qf1,  g_wq_f1);
    cudaGetSymbolAddress((void**)&qf2,  g_wq_f2);
    cudaGetSymbolAddress((void**)&wpk1, g_wpack1);
    cudaGetSymbolAddress((void**)&wpk2, g_wpack2);

    prep_kernel<<<1, 256>>>(wp1, wf1, wp2, wf2);                    // launch 0
    kmax_x<<<2048, 256>>>(x);                                       // launch 1
    conv1x1_kernel<<<dim3(512, 16), 256>>>(x, bufA, wpk1, 0, 0, 1); // launch 2
    dwconv_kernel<<<dim3(128, 16), 256>>>(bufA, bufB, qf1, a1, nullptr, 1, 2); // 3
    noop_kernel<<<1, 32>>>();                                       // launch 4 (ncu alignment)
    conv1x1_kernel<<<dim3(512, 16), 256>>>(bufB, bufA, wpk2, 1, 2, 3); // launch 5 <- profiled
    dwconv_kernel<<<dim3(128, 16), 256>>>(bufA, out, qf2, a2, x, 3, -1); // launch 6
}